// round 3
// baseline (speedup 1.0000x reference)
#include <cuda_runtime.h>

#define NBINS 100
#define EPSF 1e-10f

static __device__ float g_hist[NBINS];
static __device__ float g_wss[NBINS];

#define TPB 128            // 4 warps per block
#define WARPS 4
#define GRID 296           // 2 blocks/SM * 148 SMs
#define F2_PER_WARP (NBINS * 32)            // float2 entries per warp region
#define SMEM_BYTES (WARPS * F2_PER_WARP * 8) // 102,400 B

__global__ void init_kernel() {
    int t = threadIdx.x;
    if (t < NBINS) { g_hist[t] = 0.0f; g_wss[t] = 0.0f; }
}

__global__ void __launch_bounds__(TPB, 2)
hist_kernel(const float* __restrict__ sim, const float* __restrict__ wgt, int n)
{
    extern __shared__ float2 hw_all[];
    const int tid  = threadIdx.x;
    const int lane = tid & 31;
    const int wg   = tid >> 5;
    float2* hw = hw_all + wg * F2_PER_WARP;   // float2 hw[NBINS][32]

    // zero own column (bank-exclusive: addr = (b*32+lane)*8 -> bank 2*lane)
    #pragma unroll
    for (int b = 0; b < NBINS; b++) hw[b * 32 + lane] = make_float2(0.0f, 0.0f);
    // each lane only ever touches its own column; no sync needed

    const float4* __restrict__ sim4 = (const float4*)sim;
    const float4* __restrict__ w4   = (const float4*)wgt;
    const int n4 = n >> 2;
    const int stride = GRID * TPB;

    for (int i = blockIdx.x * TPB + tid; i < n4; i += stride) {
        float4 o = sim4[i];
        float4 w = w4[i];
        #pragma unroll
        for (int k = 0; k < 4; k++) {
            float obs = (k == 0) ? o.x : (k == 1) ? o.y : (k == 2) ? o.z : o.w;
            float wv  = (k == 0) ? w.x : (k == 1) ? w.y : (k == 2) ? w.z : w.w;
            float x = obs * 100.0f;
            int   j = (int)x;                 // x >= 0 -> trunc == floor
            float f = x - (float)j;
            float ws = wv * f;                // -> bin j+1, valid if j <= 97
            float wp = wv - ws;               // -> bin j,   valid if 1 <= j <= 98
            if (j > 97) ws = 0.0f;
            if (j < 1 || j > 98) wp = 0.0f;
            int jc = (j > 98) ? 98 : j;       // j >= 0 here

            float2 a = hw[jc * 32 + lane];
            a.x += wp; a.y = fmaf(wp, wp, a.y);
            hw[jc * 32 + lane] = a;

            float2 b2 = hw[(jc + 1) * 32 + lane];
            b2.x += ws; b2.y = fmaf(ws, ws, b2.y);
            hw[(jc + 1) * 32 + lane] = b2;
        }
    }

    // tail (n not multiple of 4): handled directly with global atomics
    if (blockIdx.x == 0 && tid < (n & 3)) {
        int idx = (n4 << 2) + tid;
        float obs = sim[idx], wv = wgt[idx];
        float x = obs * 100.0f;
        int   j = (int)x;
        float f = x - (float)j;
        float ws = wv * f;
        float wp = wv - ws;
        if (j > 97) ws = 0.0f;
        if (j < 1 || j > 98) wp = 0.0f;
        int jc = (j > 98) ? 98 : j;
        atomicAdd(&g_hist[jc], wp);     atomicAdd(&g_wss[jc], wp * wp);
        atomicAdd(&g_hist[jc + 1], ws); atomicAdd(&g_wss[jc + 1], ws * ws);
    }

    // per-warp reduction of its own region: conflict-free column loads + shuffles
    for (int b = 0; b < NBINS; b++) {
        float2 v = hw[b * 32 + lane];
        #pragma unroll
        for (int off = 16; off; off >>= 1) {
            v.x += __shfl_down_sync(0xffffffffu, v.x, off);
            v.y += __shfl_down_sync(0xffffffffu, v.y, off);
        }
        if (lane == 0) {
            atomicAdd(&g_hist[b], v.x);
            atomicAdd(&g_wss[b], v.y);
        }
    }
}

__global__ void finalize_kernel(const float* __restrict__ histo_exp,
                                float* __restrict__ out, int out_size)
{
    __shared__ float red[WARPS];
    const int t = threadIdx.x;   // 128 threads
    const int lane = t & 31, wg = t >> 5;

    float h = 0.0f, wss = 0.0f, he = 0.0f;
    if (t < NBINS) { h = g_hist[t]; wss = g_wss[t]; he = histo_exp[t]; }

    // --- block sum of h ---
    float v = h;
    #pragma unroll
    for (int off = 16; off; off >>= 1) v += __shfl_down_sync(0xffffffffu, v, off);
    if (lane == 0) red[wg] = v;
    __syncthreads();
    float sum_sim = red[0] + red[1] + red[2] + red[3];
    __syncthreads();

    // --- block sum of he ---
    v = he;
    #pragma unroll
    for (int off = 16; off; off >>= 1) v += __shfl_down_sync(0xffffffffu, v, off);
    if (lane == 0) red[wg] = v;
    __syncthreads();
    float sum_exp = red[0] + red[1] + red[2] + red[3];
    __syncthreads();

    float ssE = sum_sim + EPSF;
    float seE = sum_exp + EPSF;
    float us = wss / (ssE * ssE) + EPSF;
    float ue = he * (1.0f - he / sum_exp) / (seE * seE) + EPSF;
    float d  = h / sum_sim - he / sum_exp;
    float chi = (t < NBINS) ? d * d / (us + ue) : 0.0f;

    v = chi;
    #pragma unroll
    for (int off = 16; off; off >>= 1) v += __shfl_down_sync(0xffffffffu, v, off);
    if (lane == 0) red[wg] = v;
    __syncthreads();
    float loss = red[0] + red[1] + red[2] + red[3];

    for (int i = t; i < out_size; i += blockDim.x) out[i] = loss;
}

extern "C" void kernel_launch(void* const* d_in, const int* in_sizes, int n_in,
                              void* d_out, int out_size)
{
    const float* sim = (const float*)d_in[0];
    // d_in[1] = exp_observable (unused by fixed_binning branch)
    const float* wgt = (const float*)d_in[2];
    // d_in[3] = bins (uniform [0,1], 101 entries) -- recomputed analytically
    const float* histo_exp = (const float*)d_in[4];
    float* out = (float*)d_out;
    int n = in_sizes[0];

    static int smem_set = 0;
    (void)smem_set;
    cudaFuncSetAttribute(hist_kernel, cudaFuncAttributeMaxDynamicSharedMemorySize,
                         SMEM_BYTES);

    init_kernel<<<1, 128>>>();
    hist_kernel<<<GRID, TPB, SMEM_BYTES>>>(sim, wgt, n);
    finalize_kernel<<<1, 128>>>(histo_exp, out, out_size);
}

// round 9
// speedup vs baseline: 1.3084x; 1.3084x over previous
#include <cuda_runtime.h>

#define NBINS 100
#define BINS_PAD 101       // unconditional scheme touches bins 0..100
#define EPSF 1e-10f

static __device__ float g_hist[NBINS];
static __device__ float g_wss[NBINS];

#define TPB 256            // 8 warps per block
#define WARPS 8
#define GRID 148           // 1 block/SM
#define PLANE (BINS_PAD * 32)                   // floats per plane (3232)
#define FLOATS_PER_WARP (2 * PLANE)             // hist + wss = 6464 floats
#define SMEM_BYTES (WARPS * FLOATS_PER_WARP * 4)  // 206,848 B

#define MAGIC 12582912.0f  // 1.5*2^23 : y = x + MAGIC -> rn(x) in low mantissa

__global__ void init_kernel() {
    int t = threadIdx.x;
    if (t < NBINS) { g_hist[t] = 0.0f; g_wss[t] = 0.0f; }
}

// exact floor split: j = floor(100*obs) in [0,99], f in [0,1)
// ws -> bin j+1, wp -> bin j
__device__ __forceinline__ void bin_split(float obs, float wv,
                                          int& j, float& ws, float& wp)
{
    float y  = fmaf(obs, 100.0f, MAGIC);       // MAGIC + rn(100*obs)
    int   j0 = __float_as_int(y) & 0x1FF;      // rn(x) in [0,100]
    float t  = y - MAGIC;                      // (float)j0, exact
    float f0 = fmaf(obs, 100.0f, -t);          // x - j0 in [-0.5, 0.5]
    bool  nf = f0 < 0.0f;
    j  = j0 - (nf ? 1 : 0);                    // floor(x) in [0,99]
    float f = f0 + (nf ? 1.0f : 0.0f);         // frac in [0,1)
    ws = wv * f;
    wp = wv - ws;
}

__global__ void __launch_bounds__(TPB, 1)
hist_kernel(const float* __restrict__ sim, const float* __restrict__ wgt, int n)
{
    extern __shared__ float smem[];
    const int tid  = threadIdx.x;
    const int lane = tid & 31;
    const int wg   = tid >> 5;
    float* __restrict__ hist = smem + wg * FLOATS_PER_WARP;  // [101][32]
    float* __restrict__ wss  = hist + PLANE;                 // [101][32]

    // zero own column only (lane-exclusive; no sync needed anywhere:
    // each lane reads/writes ONLY column `lane` of its warp's planes)
    for (int b = 0; b < BINS_PAD; b++) {
        hist[b * 32 + lane] = 0.0f;
        wss [b * 32 + lane] = 0.0f;
    }

    const float4* __restrict__ sim4 = (const float4*)sim;
    const float4* __restrict__ w4   = (const float4*)wgt;
    const int n4 = n >> 2;
    const int S  = GRID * TPB;
    int i = blockIdx.x * TPB + tid;

    // software pipeline, depth 3 (current + 2 ahead in regs, fetch 3 ahead)
    float4 z = make_float4(0.f, 0.f, 0.f, 0.f);
    float4 o0 = z, w0 = z, o1 = z, w1 = z, o2 = z, w2 = z;
    if (i           < n4) { o0 = sim4[i];         w0 = w4[i];         }
    if (i + S       < n4) { o1 = sim4[i + S];     w1 = w4[i + S];     }
    if (i + 2 * S   < n4) { o2 = sim4[i + 2 * S]; w2 = w4[i + 2 * S]; }

    #pragma unroll 3
    for (; i < n4; i += S) {
        // prefetch iteration i+3S (clamped; redundant loads at the end are harmless)
        int ip = i + 3 * S;
        int ipc = ip < n4 ? ip : (n4 - 1);
        float4 on = sim4[ipc];
        float4 wn = w4[ipc];

        // process the 4 elements of o0/w0 (exclusive column -> race-free;
        // per-element the 4 smem addresses are distinct -> 4 batched LDS
        // then 4 STS; cross-element ordering handled by the in-order pipe)
        #pragma unroll
        for (int k = 0; k < 4; k++) {
            float obs = (k == 0) ? o0.x : (k == 1) ? o0.y : (k == 2) ? o0.z : o0.w;
            float wv  = (k == 0) ? w0.x : (k == 1) ? w0.y : (k == 2) ? w0.z : w0.w;
            int j; float ws_, wp_;
            bin_split(obs, wv, j, ws_, wp_);
            int a = j * 32 + lane;
            float h0 = hist[a], h1 = hist[a + 32];
            float s0 = wss [a], s1 = wss [a + 32];
            h0 += wp_;
            h1 += ws_;
            s0 = fmaf(wp_, wp_, s0);
            s1 = fmaf(ws_, ws_, s1);
            hist[a] = h0; hist[a + 32] = h1;
            wss [a] = s0; wss [a + 32] = s1;
        }

        o0 = o1; w0 = w1;
        o1 = o2; w1 = w2;
        o2 = on; w2 = wn;
    }

    // tail (n not multiple of 4): masked, straight to global atomics
    if (blockIdx.x == 0 && tid < (n & 3)) {
        int idx = (n4 << 2) + tid;
        float obs = sim[idx], wv = wgt[idx];
        int j; float ws_, wp_;
        bin_split(obs, wv, j, ws_, wp_);
        if (j > 97) ws_ = 0.0f;
        if (j < 1 || j > 98) wp_ = 0.0f;
        int jc = (j > 98) ? 98 : j;
        atomicAdd(&g_hist[jc], wp_);      atomicAdd(&g_wss[jc], wp_ * wp_);
        atomicAdd(&g_hist[jc + 1], ws_);  atomicAdd(&g_wss[jc + 1], ws_ * ws_);
    }

    // per-warp reduction; only bins 1..98 are real (reference bins 0 and 99
    // are exactly 0; padded bins 0, 99, 100 hold masked-out mass -> discard)
    for (int b = 1; b <= 98; b++) {
        float vh = hist[b * 32 + lane];
        float vs = wss [b * 32 + lane];
        #pragma unroll
        for (int off = 16; off; off >>= 1) {
            vh += __shfl_down_sync(0xffffffffu, vh, off);
            vs += __shfl_down_sync(0xffffffffu, vs, off);
        }
        if (lane == 0) {
            atomicAdd(&g_hist[b], vh);
            atomicAdd(&g_wss[b], vs);
        }
    }
}

__global__ void finalize_kernel(const float* __restrict__ histo_exp,
                                float* __restrict__ out, int out_size)
{
    __shared__ float red[4];
    const int t = threadIdx.x;   // 128 threads
    const int lane = t & 31, wg = t >> 5;

    float h = 0.0f, wss = 0.0f, he = 0.0f;
    if (t < NBINS) { h = g_hist[t]; wss = g_wss[t]; he = histo_exp[t]; }

    float v = h;
    #pragma unroll
    for (int off = 16; off; off >>= 1) v += __shfl_down_sync(0xffffffffu, v, off);
    if (lane == 0) red[wg] = v;
    __syncthreads();
    float sum_sim = red[0] + red[1] + red[2] + red[3];
    __syncthreads();

    v = he;
    #pragma unroll
    for (int off = 16; off; off >>= 1) v += __shfl_down_sync(0xffffffffu, v, off);
    if (lane == 0) red[wg] = v;
    __syncthreads();
    float sum_exp = red[0] + red[1] + red[2] + red[3];
    __syncthreads();

    float ssE = sum_sim + EPSF;
    float seE = sum_exp + EPSF;
    float us = wss / (ssE * ssE) + EPSF;
    float ue = he * (1.0f - he / sum_exp) / (seE * seE) + EPSF;
    float d  = h / sum_sim - he / sum_exp;
    float chi = (t < NBINS) ? d * d / (us + ue) : 0.0f;

    v = chi;
    #pragma unroll
    for (int off = 16; off; off >>= 1) v += __shfl_down_sync(0xffffffffu, v, off);
    if (lane == 0) red[wg] = v;
    __syncthreads();
    float loss = red[0] + red[1] + red[2] + red[3];

    for (int i = t; i < out_size; i += blockDim.x) out[i] = loss;
}

extern "C" void kernel_launch(void* const* d_in, const int* in_sizes, int n_in,
                              void* d_out, int out_size)
{
    const float* sim = (const float*)d_in[0];
    // d_in[1] = exp_observable (unused by fixed_binning branch)
    const float* wgt = (const float*)d_in[2];
    // d_in[3] = bins (uniform [0,1], 101 entries) -- handled analytically
    const float* histo_exp = (const float*)d_in[4];
    float* out = (float*)d_out;
    int n = in_sizes[0];

    cudaFuncSetAttribute(hist_kernel, cudaFuncAttributeMaxDynamicSharedMemorySize,
                         SMEM_BYTES);

    init_kernel<<<1, 128>>>();
    hist_kernel<<<GRID, TPB, SMEM_BYTES>>>(sim, wgt, n);
    finalize_kernel<<<1, 128>>>(histo_exp, out, out_size);
}

// round 11
// speedup vs baseline: 1.3118x; 1.0026x over previous
#include <cuda_runtime.h>

#define NBINS 100
#define BINS_PAD 101       // unconditional scheme touches bins 0..100
#define EPSF 1e-10f

static __device__ float g_hist[NBINS];
static __device__ float g_wss[NBINS];

#define TPB 256            // 8 warps per block
#define WARPS 8
#define GRID 148           // 1 block/SM
#define F2_PER_WARP (BINS_PAD * 32)              // float2 entries per warp plane
#define SMEM_BYTES (WARPS * F2_PER_WARP * 8)     // 206,848 B

#define MAGIC 12582912.0f  // 1.5*2^23 : y = x + MAGIC -> rn(x) in low mantissa
#define D 8                // chunk depth (float4-pairs per buffer)

__global__ void init_kernel() {
    int t = threadIdx.x;
    if (t < NBINS) { g_hist[t] = 0.0f; g_wss[t] = 0.0f; }
}

// exact floor split: j = floor(100*obs) in [0,99], f in [0,1)
// ws -> bin j+1, wp -> bin j
__device__ __forceinline__ void bin_split(float obs, float wv,
                                          int& j, float& ws, float& wp)
{
    float y  = fmaf(obs, 100.0f, MAGIC);       // MAGIC + rn(100*obs)
    int   j0 = __float_as_int(y) & 0x1FF;      // rn(x) in [0,100]
    float t  = y - MAGIC;                      // (float)j0, exact
    float f0 = fmaf(obs, 100.0f, -t);          // x - j0 in [-0.5, 0.5]
    bool  nf = f0 < 0.0f;
    j  = j0 - (nf ? 1 : 0);                    // floor(x) in [0,99]
    float f = f0 + (nf ? 1.0f : 0.0f);         // frac in [0,1)
    ws = wv * f;
    wp = wv - ws;
}

// one element into this lane's exclusive column (race-free by ownership;
// the two addresses j / j+1 are distinct -> 2 batched LDS.64 then 2 STS.64)
__device__ __forceinline__ void process1(float2* __restrict__ hw, int lane,
                                         float obs, float wv)
{
    int j; float ws, wp;
    bin_split(obs, wv, j, ws, wp);
    int a = j * 32 + lane;
    float2 p = hw[a];        // {hist, wss} at bin j
    float2 s = hw[a + 32];   // {hist, wss} at bin j+1
    p.x += wp; p.y = fmaf(wp, wp, p.y);
    s.x += ws; s.y = fmaf(ws, ws, s.y);
    hw[a] = p;
    hw[a + 32] = s;
}

__device__ __forceinline__ void process4(float2* __restrict__ hw, int lane,
                                         float4 o, float4 w)
{
    process1(hw, lane, o.x, w.x);
    process1(hw, lane, o.y, w.y);
    process1(hw, lane, o.z, w.z);
    process1(hw, lane, o.w, w.w);
}

__global__ void __launch_bounds__(TPB, 1)
hist_kernel(const float* __restrict__ sim, const float* __restrict__ wgt, int n)
{
    extern __shared__ float2 hw_all[];
    const int tid  = threadIdx.x;
    const int lane = tid & 31;
    const int wg   = tid >> 5;
    float2* __restrict__ hw = hw_all + wg * F2_PER_WARP;  // float2[101][32]

    // zero own column only (lane-exclusive; each lane ever touches only
    // column `lane` of its warp's plane -> no syncs needed)
    for (int b = 0; b < BINS_PAD; b++)
        hw[b * 32 + lane] = make_float2(0.0f, 0.0f);

    const float4* __restrict__ sim4 = (const float4*)sim;
    const float4* __restrict__ w4   = (const float4*)wgt;
    const int n4 = n >> 2;
    const int S  = GRID * TPB;
    const int i0 = blockIdx.x * TPB + tid;
    const int NCH = n4 / (D * S);       // full (unmasked) chunks

    float4 oA[D], wA[D], oB[D], wB[D];

    if (NCH > 0) {
        // preload chunk 0 -> A  (16 independent LDG.128, front-batched)
        #pragma unroll
        for (int d = 0; d < D; d++) {
            oA[d] = sim4[i0 + d * S];
            wA[d] = w4  [i0 + d * S];
        }
        int c = 0;
        while (true) {
            if (c + 1 < NCH) {                    // load chunk c+1 -> B
                int b2 = i0 + (c + 1) * (D * S);
                #pragma unroll
                for (int d = 0; d < D; d++) {
                    oB[d] = sim4[b2 + d * S];
                    wB[d] = w4  [b2 + d * S];
                }
            }
            #pragma unroll
            for (int d = 0; d < D; d++) process4(hw, lane, oA[d], wA[d]);
            c++;
            if (c >= NCH) break;

            if (c + 1 < NCH) {                    // load chunk c+1 -> A
                int b2 = i0 + (c + 1) * (D * S);
                #pragma unroll
                for (int d = 0; d < D; d++) {
                    oA[d] = sim4[b2 + d * S];
                    wA[d] = w4  [b2 + d * S];
                }
            }
            #pragma unroll
            for (int d = 0; d < D; d++) process4(hw, lane, oB[d], wB[d]);
            c++;
            if (c >= NCH) break;
        }
    }

    // remainder float4 slots (masked, depth-1; ~6 iterations per thread)
    for (int i = i0 + NCH * (D * S); i < n4; i += S) {
        float4 o = sim4[i];
        float4 w = w4[i];
        process4(hw, lane, o, w);
    }

    // scalar tail (n not multiple of 4): straight to global atomics
    if (blockIdx.x == 0 && tid < (n & 3)) {
        int idx = (n4 << 2) + tid;
        float obs = sim[idx], wv = wgt[idx];
        int j; float ws_, wp_;
        bin_split(obs, wv, j, ws_, wp_);
        if (j > 97) ws_ = 0.0f;
        if (j < 1 || j > 98) wp_ = 0.0f;
        int jc = (j > 98) ? 98 : j;
        atomicAdd(&g_hist[jc], wp_);      atomicAdd(&g_wss[jc], wp_ * wp_);
        atomicAdd(&g_hist[jc + 1], ws_);  atomicAdd(&g_wss[jc + 1], ws_ * ws_);
    }

    // per-warp reduction; only bins 1..98 are real (reference bins 0 and 99
    // are exactly 0; padded bins 0, 99, 100 hold masked-out mass -> discard)
    for (int b = 1; b <= 98; b++) {
        float2 v = hw[b * 32 + lane];
        #pragma unroll
        for (int off = 16; off; off >>= 1) {
            v.x += __shfl_down_sync(0xffffffffu, v.x, off);
            v.y += __shfl_down_sync(0xffffffffu, v.y, off);
        }
        if (lane == 0) {
            atomicAdd(&g_hist[b], v.x);
            atomicAdd(&g_wss[b], v.y);
        }
    }
}

__global__ void finalize_kernel(const float* __restrict__ histo_exp,
                                float* __restrict__ out, int out_size)
{
    __shared__ float red[4];
    const int t = threadIdx.x;   // 128 threads
    const int lane = t & 31, wg = t >> 5;

    float h = 0.0f, wss = 0.0f, he = 0.0f;
    if (t < NBINS) { h = g_hist[t]; wss = g_wss[t]; he = histo_exp[t]; }

    float v = h;
    #pragma unroll
    for (int off = 16; off; off >>= 1) v += __shfl_down_sync(0xffffffffu, v, off);
    if (lane == 0) red[wg] = v;
    __syncthreads();
    float sum_sim = red[0] + red[1] + red[2] + red[3];
    __syncthreads();

    v = he;
    #pragma unroll
    for (int off = 16; off; off >>= 1) v += __shfl_down_sync(0xffffffffu, v, off);
    if (lane == 0) red[wg] = v;
    __syncthreads();
    float sum_exp = red[0] + red[1] + red[2] + red[3];
    __syncthreads();

    float ssE = sum_sim + EPSF;
    float seE = sum_exp + EPSF;
    float us = wss / (ssE * ssE) + EPSF;
    float ue = he * (1.0f - he / sum_exp) / (seE * seE) + EPSF;
    float d  = h / sum_sim - he / sum_exp;
    float chi = (t < NBINS) ? d * d / (us + ue) : 0.0f;

    v = chi;
    #pragma unroll
    for (int off = 16; off; off >>= 1) v += __shfl_down_sync(0xffffffffu, v, off);
    if (lane == 0) red[wg] = v;
    __syncthreads();
    float loss = red[0] + red[1] + red[2] + red[3];

    for (int i = t; i < out_size; i += blockDim.x) out[i] = loss;
}

extern "C" void kernel_launch(void* const* d_in, const int* in_sizes, int n_in,
                              void* d_out, int out_size)
{
    const float* sim = (const float*)d_in[0];
    // d_in[1] = exp_observable (unused by fixed_binning branch)
    const float* wgt = (const float*)d_in[2];
    // d_in[3] = bins (uniform [0,1], 101 entries) -- handled analytically
    const float* histo_exp = (const float*)d_in[4];
    float* out = (float*)d_out;
    int n = in_sizes[0];

    cudaFuncSetAttribute(hist_kernel, cudaFuncAttributeMaxDynamicSharedMemorySize,
                         SMEM_BYTES);

    init_kernel<<<1, 128>>>();
    hist_kernel<<<GRID, TPB, SMEM_BYTES>>>(sim, wgt, n);
    finalize_kernel<<<1, 128>>>(histo_exp, out, out_size);
}